// round 16
// baseline (speedup 1.0000x reference)
#include <cuda_runtime.h>

#define NTHREADS 128   // threads 0..97 each compute patches 2t, 2t+1

typedef unsigned long long u64;

__device__ __forceinline__ u64 mul2(u64 a, u64 b) {
    u64 d; asm("mul.rn.f32x2 %0,%1,%2;" : "=l"(d) : "l"(a), "l"(b)); return d;
}
__device__ __forceinline__ u64 add2(u64 a, u64 b) {
    u64 d; asm("add.rn.f32x2 %0,%1,%2;" : "=l"(d) : "l"(a), "l"(b)); return d;
}
__device__ __forceinline__ u64 fma2(u64 a, u64 b, u64 c) {
    u64 d; asm("fma.rn.f32x2 %0,%1,%2,%3;" : "=l"(d) : "l"(a), "l"(b), "l"(c)); return d;
}
__device__ __forceinline__ u64 pk2(float lo, float hi) {
    u64 d; asm("mov.b64 %0,{%1,%2};" : "=l"(d) : "f"(lo), "f"(hi)); return d;
}
__device__ __forceinline__ void upk(u64 v, float& lo, float& hi) {
    asm("mov.b64 {%0,%1},%2;" : "=f"(lo), "=f"(hi) : "l"(v));
}
__device__ __forceinline__ u64 neg1pk() {
    u64 d; asm("mov.b64 %0,0xBF800000BF800000;" : "=l"(d)); return d;
}

// Full circuit for one patch given its 4 raw angles; returns z-vec (z0,z1,z2,z3).
__device__ __forceinline__ float4 patch_circuit(
    float a0, float a1, float a2, float a3,
    const float* p0h, const u64* cP, const u64* sP, const u64* nsP,
    u64 csa, u64 csb)
{
    float cc[4], ss[4];
    __sincosf(fmaf(a0, 0.5f, p0h[0]), &ss[0], &cc[0]);
    __sincosf(fmaf(a1, 0.5f, p0h[1]), &ss[1], &cc[1]);
    __sincosf(fmaf(a2, 0.5f, p0h[2]), &ss[2], &cc[2]);
    __sincosf(fmaf(a3, 0.5f, p0h[3]), &ss[3], &cc[3]);

    const u64 C0 = pk2(cc[0], cc[0]), S0 = pk2(ss[0], ss[0]);
    const u64 C1 = pk2(cc[1], cc[1]), S1 = pk2(ss[1], ss[1]);
    const u64 C2 = pk2(cc[2], cc[2]), S2 = pk2(ss[2], ss[2]);
    const u64 C3 = pk2(cc[3], cc[3]), S3 = pk2(ss[3], ss[3]);

    // a23 table with layer-1 Ry(wire2) folded in
    u64 D23[4];
    D23[0] = mul2(C2, C3); D23[1] = mul2(C2, S3);
    D23[2] = mul2(S2, C3); D23[3] = mul2(S2, S3);
    u64 B23[4];
    #pragma unroll
    for (int y = 0; y < 4; y++)
        B23[y] = fma2(csa, D23[y], mul2(csb, D23[y ^ 3]));

    u64 A01[4];
    A01[0] = mul2(C0, C1); A01[1] = mul2(C0, S1);
    A01[2] = mul2(S0, C1); A01[3] = mul2(S0, S1);

    // Product state, layer-0 CNOTs folded (label permutation), pack lane = q2
    u64 P[8];
    #pragma unroll
    for (int k = 0; k < 8; k++) {
        const int u0 = (k >> 2) & 1, u1 = (k >> 1) & 1, u3 = k & 1;
        const int xa = ((u0 ^ u3) << 1) | (u0 ^ u1 ^ u3);
        const int y  = (u1 << 1) | u3;
        P[k] = mul2(A01[xa], B23[y]);
    }

    // Layer-1 Ry wires 0 (bit4), 1 (bit2), 3 (bit1) — packed
    #pragma unroll
    for (int wsel = 0; wsel < 3; wsel++) {
        const int kb = (wsel == 0) ? 4 : (wsel == 1) ? 2 : 1;
        const int w  = (wsel == 2) ? 3 : wsel;
        const u64 cv = cP[w], sv = sP[w], nsv = nsP[w];
        #pragma unroll
        for (int k = 0; k < 8; k++) {
            if (!(k & kb)) {
                u64 q0 = P[k], q1 = P[k | kb];
                P[k]      = fma2(nsv, q1, mul2(cv, q0));
                P[k | kb] = fma2(cv,  q1, mul2(sv, q0));
            }
        }
    }

    // Measurement, layer-1 CNOTs folded into sign masks
    const u64 NEG1 = neg1pk();
    #define SUB2(a, bb) fma2((bb), NEG1, (a))
    u64 Q[8];
    #pragma unroll
    for (int k = 0; k < 8; k++) Q[k] = mul2(P[k], P[k]);

    u64 Sp[4], Sm[4];
    #pragma unroll
    for (int j = 0; j < 4; j++) { Sp[j] = add2(Q[j], Q[j+4]); Sm[j] = SUB2(Q[j], Q[j+4]); }

    u64 z0p = SUB2(SUB2(Sp[0], Sp[1]), SUB2(Sp[2], Sp[3]));
    u64 z1p = SUB2(add2(Sm[0], Sm[1]), add2(Sm[2], Sm[3]));
    u64 z3p = SUB2(SUB2(Sm[0], Sm[1]), SUB2(Sm[2], Sm[3]));
    #undef SUB2

    float l0, h0, l1, h1, l3, h3;
    upk(z0p, l0, h0); upk(z1p, l1, h1); upk(z3p, l3, h3);
    float4 z;
    z.x = l0 - h0;
    z.y = l1 + h1;
    z.z = l1 - h1;
    z.w = l3 - h3;
    return z;
}

__global__ __launch_bounds__(NTHREADS, 12)
void quanv_kernel(const float* __restrict__ x,
                  const float* __restrict__ params,
                  const float* __restrict__ W,
                  const float* __restrict__ bias,
                  float* __restrict__ out)
{
    __shared__ float p0h[4];                 // layer-0 params * 0.5
    __shared__ u64  cP[4], sP[4], nsP[4];    // packed consts wires 0,1,3
    __shared__ u64  csa_s, csb_s;            // wire-2 fold
    __shared__ float wsum[4][10];

    const int b = blockIdx.x;
    const int t = threadIdx.x;
    const int lane = t & 31;

    if (t < 4) {
        p0h[t] = params[t] * 0.5f;
        float sv, cv;
        __sincosf(params[4 + t] * 0.5f, &sv, &cv);
        if (t == 2) { csa_s = pk2(cv, sv); csb_s = pk2(-sv, cv); }
        else        { cP[t] = pk2(cv, cv); sP[t] = pk2(sv, sv); nsP[t] = pk2(-sv, -sv); }
    }
    __syncthreads();

    float vals[16];
    #pragma unroll
    for (int c = 0; c < 16; c++) vals[c] = 0.0f;

    if (t < 98) {
        // Patch pair (2t, 2t+1): same row pair, 4 consecutive image columns.
        const int p0 = 2 * t;
        const int pr = p0 / 14, pc = p0 % 14;     // pc even
        const float* px = x + b * 784 + pr * 56 + pc * 2;   // 16B-aligned
        const float4 R0 = *reinterpret_cast<const float4*>(px);
        const float4 R1 = *reinterpret_cast<const float4*>(px + 28);

        const u64 csa = csa_s, csb = csb_s;
        const float4 za = patch_circuit(R0.x, R0.y, R1.x, R1.y, p0h, cP, sP, nsP, csa, csb);
        const float4 zb = patch_circuit(R0.z, R0.w, R1.z, R1.w, p0h, cP, sP, nsP, csa, csb);

        // Merged W-dot: pair reads 32 contiguous bytes per class.
        const u64 za01 = pk2(za.x, za.y), za23 = pk2(za.z, za.w);
        const u64 zb01 = pk2(zb.x, zb.y), zb23 = pk2(zb.z, zb.w);
        #pragma unroll
        for (int c = 0; c < 10; c++) {
            const float* wr = W + c * 784 + 8 * t;
            u64 wa01, wa23, wb01, wb23;
            asm("ld.global.nc.v2.b64 {%0,%1},[%2];"
                : "=l"(wa01), "=l"(wa23) : "l"(wr));
            asm("ld.global.nc.v2.b64 {%0,%1},[%2];"
                : "=l"(wb01), "=l"(wb23) : "l"(wr + 4));
            u64 acc = fma2(za23, wa23, mul2(za01, wa01));
            acc = fma2(zb01, wb01, acc);
            acc = fma2(zb23, wb23, acc);
            float alo, ahi; upk(acc, alo, ahi);
            vals[c] = alo + ahi;
        }
    }

    // Multi-value butterfly over 4 warps: split the class set each stage.
    #pragma unroll
    for (int stage = 0; stage < 4; stage++) {
        const int m = 1 << stage;
        const int h = 8 >> stage;
        const bool hi = (lane & m) != 0;
        #pragma unroll
        for (int c = 0; c < h; c++) {
            float send = hi ? vals[c]     : vals[c + h];
            float keep = hi ? vals[c + h] : vals[c];
            vals[c] = keep + __shfl_xor_sync(0xffffffffu, send, m);
        }
    }
    vals[0] += __shfl_xor_sync(0xffffffffu, vals[0], 16);

    const int cls = __brev(lane) >> 28;   // bitrev4 of lane&15
    if (lane < 16 && cls < 10) wsum[t >> 5][cls] = vals[0];
    __syncthreads();

    // Warp 0: combine 4 rows + log_softmax via shuffles (logits tiny; no max-shift).
    if (t < 32) {
        float logit = 0.0f, e = 0.0f;
        if (t < 10) {
            float v = bias[t];
            #pragma unroll
            for (int w = 0; w < 4; w++) v += wsum[w][t];
            logit = v;
            e = __expf(v);
        }
        #pragma unroll
        for (int off = 8; off > 0; off >>= 1)
            e += __shfl_xor_sync(0xffffffffu, e, off);
        if (t < 10) out[b * 10 + t] = logit - __logf(e);
    }
}

extern "C" void kernel_launch(void* const* d_in, const int* in_sizes, int n_in,
                              void* d_out, int out_size) {
    const float* x      = (const float*)d_in[0];   // [8192, 28, 28]
    const float* params = (const float*)d_in[1];   // [2, 4]
    const float* W      = (const float*)d_in[2];   // [10, 784]
    const float* bias   = (const float*)d_in[3];   // [10]
    float* out          = (float*)d_out;           // [8192, 10]

    const int B = in_sizes[0] / 784;
    quanv_kernel<<<B, NTHREADS>>>(x, params, W, bias, out);
}

// round 17
// speedup vs baseline: 1.2653x; 1.2653x over previous
#include <cuda_runtime.h>

#define NTHREADS 128   // threads 0..97: patch-pair (2t,2t+1) for BOTH images of the block

typedef unsigned long long u64;

__device__ __forceinline__ u64 mul2(u64 a, u64 b) {
    u64 d; asm("mul.rn.f32x2 %0,%1,%2;" : "=l"(d) : "l"(a), "l"(b)); return d;
}
__device__ __forceinline__ u64 add2(u64 a, u64 b) {
    u64 d; asm("add.rn.f32x2 %0,%1,%2;" : "=l"(d) : "l"(a), "l"(b)); return d;
}
__device__ __forceinline__ u64 fma2(u64 a, u64 b, u64 c) {
    u64 d; asm("fma.rn.f32x2 %0,%1,%2,%3;" : "=l"(d) : "l"(a), "l"(b), "l"(c)); return d;
}
__device__ __forceinline__ u64 pk2(float lo, float hi) {
    u64 d; asm("mov.b64 %0,{%1,%2};" : "=l"(d) : "f"(lo), "f"(hi)); return d;
}
__device__ __forceinline__ void upk(u64 v, float& lo, float& hi) {
    asm("mov.b64 {%0,%1},%2;" : "=f"(lo), "=f"(hi) : "l"(v));
}
__device__ __forceinline__ u64 neg1pk() {
    u64 d; asm("mov.b64 %0,0xBF800000BF800000;" : "=l"(d)); return d;
}

// Full circuit for one patch given its 4 raw angles; returns (z0,z1,z2,z3).
__device__ __forceinline__ float4 patch_circuit(
    float a0, float a1, float a2, float a3,
    const float* p0h, const u64* cP, const u64* sP, const u64* nsP,
    u64 csa, u64 csb)
{
    float cc[4], ss[4];
    __sincosf(fmaf(a0, 0.5f, p0h[0]), &ss[0], &cc[0]);
    __sincosf(fmaf(a1, 0.5f, p0h[1]), &ss[1], &cc[1]);
    __sincosf(fmaf(a2, 0.5f, p0h[2]), &ss[2], &cc[2]);
    __sincosf(fmaf(a3, 0.5f, p0h[3]), &ss[3], &cc[3]);

    const u64 C0 = pk2(cc[0], cc[0]), S0 = pk2(ss[0], ss[0]);
    const u64 C1 = pk2(cc[1], cc[1]), S1 = pk2(ss[1], ss[1]);
    const u64 C2 = pk2(cc[2], cc[2]), S2 = pk2(ss[2], ss[2]);
    const u64 C3 = pk2(cc[3], cc[3]), S3 = pk2(ss[3], ss[3]);

    // a23 table with layer-1 Ry(wire2) folded in
    u64 D23[4];
    D23[0] = mul2(C2, C3); D23[1] = mul2(C2, S3);
    D23[2] = mul2(S2, C3); D23[3] = mul2(S2, S3);
    u64 B23[4];
    #pragma unroll
    for (int y = 0; y < 4; y++)
        B23[y] = fma2(csa, D23[y], mul2(csb, D23[y ^ 3]));

    u64 A01[4];
    A01[0] = mul2(C0, C1); A01[1] = mul2(C0, S1);
    A01[2] = mul2(S0, C1); A01[3] = mul2(S0, S1);

    // Product state, layer-0 CNOTs folded (label permutation), pack lane = q2
    u64 P[8];
    #pragma unroll
    for (int k = 0; k < 8; k++) {
        const int u0 = (k >> 2) & 1, u1 = (k >> 1) & 1, u3 = k & 1;
        const int xa = ((u0 ^ u3) << 1) | (u0 ^ u1 ^ u3);
        const int y  = (u1 << 1) | u3;
        P[k] = mul2(A01[xa], B23[y]);
    }

    // Layer-1 Ry wires 0 (bit4), 1 (bit2), 3 (bit1) — packed
    #pragma unroll
    for (int wsel = 0; wsel < 3; wsel++) {
        const int kb = (wsel == 0) ? 4 : (wsel == 1) ? 2 : 1;
        const int w  = (wsel == 2) ? 3 : wsel;
        const u64 cv = cP[w], sv = sP[w], nsv = nsP[w];
        #pragma unroll
        for (int k = 0; k < 8; k++) {
            if (!(k & kb)) {
                u64 q0 = P[k], q1 = P[k | kb];
                P[k]      = fma2(nsv, q1, mul2(cv, q0));
                P[k | kb] = fma2(cv,  q1, mul2(sv, q0));
            }
        }
    }

    // Measurement, layer-1 CNOTs folded into sign masks
    const u64 NEG1 = neg1pk();
    #define SUB2(a, bb) fma2((bb), NEG1, (a))
    u64 Q[8];
    #pragma unroll
    for (int k = 0; k < 8; k++) Q[k] = mul2(P[k], P[k]);

    u64 Sp[4], Sm[4];
    #pragma unroll
    for (int j = 0; j < 4; j++) { Sp[j] = add2(Q[j], Q[j+4]); Sm[j] = SUB2(Q[j], Q[j+4]); }

    u64 z0p = SUB2(SUB2(Sp[0], Sp[1]), SUB2(Sp[2], Sp[3]));
    u64 z1p = SUB2(add2(Sm[0], Sm[1]), add2(Sm[2], Sm[3]));
    u64 z3p = SUB2(SUB2(Sm[0], Sm[1]), SUB2(Sm[2], Sm[3]));
    #undef SUB2

    float l0, h0, l1, h1, l3, h3;
    upk(z0p, l0, h0); upk(z1p, l1, h1); upk(z3p, l3, h3);
    float4 z;
    z.x = l0 - h0;
    z.y = l1 + h1;
    z.z = l1 - h1;
    z.w = l3 - h3;
    return z;
}

__global__ __launch_bounds__(NTHREADS)
void quanv_kernel(const float* __restrict__ x,
                  const float* __restrict__ params,
                  const float* __restrict__ W,
                  const float* __restrict__ bias,
                  float* __restrict__ out)
{
    __shared__ float p0h[4];                 // layer-0 params * 0.5
    __shared__ u64  cP[4], sP[4], nsP[4];    // packed consts wires 0,1,3
    __shared__ u64  csa_s, csb_s;            // wire-2 fold
    __shared__ float wsum[2][4][10];         // [image][warp][class]

    const int b = blockIdx.x;                // image pair (2b, 2b+1)
    const int t = threadIdx.x;
    const int lane = t & 31;

    if (t < 4) {
        p0h[t] = params[t] * 0.5f;
        float sv, cv;
        __sincosf(params[4 + t] * 0.5f, &sv, &cv);
        if (t == 2) { csa_s = pk2(cv, sv); csb_s = pk2(-sv, cv); }
        else        { cP[t] = pk2(cv, cv); sP[t] = pk2(sv, sv); nsP[t] = pk2(-sv, -sv); }
    }
    __syncthreads();

    float vals0[16], vals1[16];
    #pragma unroll
    for (int c = 0; c < 16; c++) { vals0[c] = 0.0f; vals1[c] = 0.0f; }

    if (t < 98) {
        // Patch pair (2t, 2t+1): same row pair, 4 consecutive image columns.
        const int p0 = 2 * t;
        const int pr = p0 / 14, pc = p0 % 14;     // pc even
        const float* px0 = x + (2 * b) * 784 + pr * 56 + pc * 2;   // 16B-aligned
        const u64 csa = csa_s, csb = csb_s;

        // Image 0 circuits
        const float4 A0 = *reinterpret_cast<const float4*>(px0);
        const float4 A1 = *reinterpret_cast<const float4*>(px0 + 28);
        const float4 za = patch_circuit(A0.x, A0.y, A1.x, A1.y, p0h, cP, sP, nsP, csa, csb);
        const float4 zb = patch_circuit(A0.z, A0.w, A1.z, A1.w, p0h, cP, sP, nsP, csa, csb);
        const u64 za01 = pk2(za.x, za.y), za23 = pk2(za.z, za.w);
        const u64 zb01 = pk2(zb.x, zb.y), zb23 = pk2(zb.z, zb.w);

        // Image 1 circuits (same patch positions)
        const float4 B0 = *reinterpret_cast<const float4*>(px0 + 784);
        const float4 B1 = *reinterpret_cast<const float4*>(px0 + 784 + 28);
        const float4 zc = patch_circuit(B0.x, B0.y, B1.x, B1.y, p0h, cP, sP, nsP, csa, csb);
        const float4 zd = patch_circuit(B0.z, B0.w, B1.z, B1.w, p0h, cP, sP, nsP, csa, csb);
        const u64 zc01 = pk2(zc.x, zc.y), zc23 = pk2(zc.z, zc.w);
        const u64 zd01 = pk2(zd.x, zd.y), zd23 = pk2(zd.z, zd.w);

        // W-dot: each W chunk loaded ONCE, used for BOTH images.
        #pragma unroll
        for (int c = 0; c < 10; c++) {
            const float* wr = W + c * 784 + 8 * t;
            u64 wa01, wa23, wb01, wb23;
            asm("ld.global.nc.v2.b64 {%0,%1},[%2];"
                : "=l"(wa01), "=l"(wa23) : "l"(wr));
            asm("ld.global.nc.v2.b64 {%0,%1},[%2];"
                : "=l"(wb01), "=l"(wb23) : "l"(wr + 4));

            u64 acc0 = fma2(za23, wa23, mul2(za01, wa01));
            acc0 = fma2(zb01, wb01, acc0);
            acc0 = fma2(zb23, wb23, acc0);
            float a0lo, a0hi; upk(acc0, a0lo, a0hi);
            vals0[c] = a0lo + a0hi;

            u64 acc1 = fma2(zc23, wa23, mul2(zc01, wa01));
            acc1 = fma2(zd01, wb01, acc1);
            acc1 = fma2(zd23, wb23, acc1);
            float a1lo, a1hi; upk(acc1, a1lo, a1hi);
            vals1[c] = a1lo + a1hi;
        }
    }

    // Two multi-value butterflies (one per image), 4 warps each.
    #pragma unroll
    for (int im = 0; im < 2; im++) {
        float* vals = im ? vals1 : vals0;
        #pragma unroll
        for (int stage = 0; stage < 4; stage++) {
            const int m = 1 << stage;
            const int h = 8 >> stage;
            const bool hi = (lane & m) != 0;
            #pragma unroll
            for (int c = 0; c < h; c++) {
                float send = hi ? vals[c]     : vals[c + h];
                float keep = hi ? vals[c + h] : vals[c];
                vals[c] = keep + __shfl_xor_sync(0xffffffffu, send, m);
            }
        }
        vals[0] += __shfl_xor_sync(0xffffffffu, vals[0], 16);
        const int cls = __brev(lane) >> 28;   // bitrev4 of lane&15
        if (lane < 16 && cls < 10) wsum[im][t >> 5][cls] = vals[0];
    }
    __syncthreads();

    // Warp 0: both images' combine + log_softmax; 16-lane halves
    // (xor offsets <=8 never cross a half).
    if (t < 32) {
        const int imo = t >> 4, c = t & 15;
        float logit = 0.0f, e = 0.0f;
        if (c < 10) {
            float v = bias[c];
            #pragma unroll
            for (int w = 0; w < 4; w++) v += wsum[imo][w][c];
            logit = v;
            e = __expf(v);           // logits tiny; no max-shift needed
        }
        #pragma unroll
        for (int off = 8; off > 0; off >>= 1)
            e += __shfl_xor_sync(0xffffffffu, e, off);
        if (c < 10) out[(2 * b + imo) * 10 + c] = logit - __logf(e);
    }
}

extern "C" void kernel_launch(void* const* d_in, const int* in_sizes, int n_in,
                              void* d_out, int out_size) {
    const float* x      = (const float*)d_in[0];   // [8192, 28, 28]
    const float* params = (const float*)d_in[1];   // [2, 4]
    const float* W      = (const float*)d_in[2];   // [10, 784]
    const float* bias   = (const float*)d_in[3];   // [10]
    float* out          = (float*)d_out;           // [8192, 10]

    const int B = in_sizes[0] / 784;
    quanv_kernel<<<B / 2, NTHREADS>>>(x, params, W, bias, out);
}